// round 1
// baseline (speedup 1.0000x reference)
#include <cuda_runtime.h>
#include <math.h>

// Problem constants (fixed shapes from the reference)
#define Bv   16      // videos
#define Cc   256     // channels
#define Nn   64      // clip grid
#define NN   4096    // Nn*Nn
#define Ss   128     // total sentences
#define EPSN 1e-12f
#define SCALE 10.0f
#define TPB  128     // threads per block in main kernel

// Scratch (no allocations allowed): normalized sentence features + offsets
__device__ float g_sn1[Ss * Cc];
__device__ float g_sn2[Ss * Cc];
__device__ int   g_off[Bv + 1];

// Packed dual-fp32 FMA (Blackwell): acc = a*b + acc, lanewise on {lo,hi}
#define FFMA2(acc, a, bb) \
    asm("fma.rn.f32x2 %0, %1, %2, %0;" : "+l"(acc) : "l"(a), "l"(bb))

__device__ __forceinline__ float f2lo(unsigned long long x) {
    return __uint_as_float((unsigned)(x & 0xffffffffu));
}
__device__ __forceinline__ float f2hi(unsigned long long x) {
    return __uint_as_float((unsigned)(x >> 32));
}

// ---------------------------------------------------------------------------
// Kernel 1: normalize sentence features (warp per row) + prefix-sum offsets.
// rows [0,S) -> sents1, rows [S,2S) -> sents2. grid = 2S/8 blocks of 256.
// ---------------------------------------------------------------------------
__global__ void prep_kernel(const float* __restrict__ sf1,
                            const float* __restrict__ sf2,
                            const int*   __restrict__ nums) {
    if (blockIdx.x == 0 && threadIdx.x == 0) {
        int acc = 0;
        g_off[0] = 0;
        #pragma unroll
        for (int i = 0; i < Bv; i++) { acc += nums[i]; g_off[i + 1] = acc; }
    }
    int warp = threadIdx.x >> 5;
    int lane = threadIdx.x & 31;
    int row  = blockIdx.x * 8 + warp;            // 2S rows total
    const float* src;
    float* dst;
    if (row < Ss) { src = sf1 + (size_t)row * Cc;        dst = g_sn1 + (size_t)row * Cc; }
    else          { src = sf2 + (size_t)(row - Ss) * Cc; dst = g_sn2 + (size_t)(row - Ss) * Cc; }

    float v[8];
    float sum = 0.f;
    #pragma unroll
    for (int k = 0; k < 8; k++) {
        v[k] = src[lane + 32 * k];
        sum += v[k] * v[k];
    }
    #pragma unroll
    for (int o = 16; o; o >>= 1) sum += __shfl_xor_sync(0xffffffffu, sum, o);
    float inv = 1.f / fmaxf(sqrtf(sum), EPSN);
    #pragma unroll
    for (int k = 0; k < 8; k++) dst[lane + 32 * k] = v[k] * inv;
}

// ---------------------------------------------------------------------------
// Kernel 2: fused dual-space scoring.
// Each thread owns 2 adjacent (i,j) columns; float2 global loads are the
// packed f32x2 operand. Sentence scalars live duplicated {v,v} in shared so
// one LDS.64 feeds one FFMA2. Both spaces + epilogue fused -> video feats
// are read exactly once from HBM.
// grid = (NN/(2*TPB), B) = (16,16), block = 128.
// ---------------------------------------------------------------------------
__global__ __launch_bounds__(TPB) void score_kernel(
    const float* __restrict__ vf1,
    const float* __restrict__ vf2,
    const float* __restrict__ mask2d,
    float* __restrict__ out) {

    __shared__ float2 sm1[8][Cc];   // 16 KB
    __shared__ float2 sm2[8][Cc];   // 16 KB

    const int b   = blockIdx.y;
    const int tid = threadIdx.x;
    const int ij0 = blockIdx.x * (2 * TPB) + 2 * tid;

    const int start = g_off[b];
    int end = (b == Bv - 1) ? Ss : g_off[b + 1];
    if (end > Ss) end = Ss;
    if (start >= end) return;   // uniform per block

    const unsigned long long* v1 = reinterpret_cast<const unsigned long long*>(
        vf1 + (size_t)b * Cc * NN + ij0);
    const unsigned long long* v2 = reinterpret_cast<const unsigned long long*>(
        vf2 + (size_t)b * Cc * NN + ij0);

    const float m0 = mask2d[ij0];
    const float m1 = mask2d[ij0 + 1];

    const unsigned long long* s1p = reinterpret_cast<const unsigned long long*>(&sm1[0][0]);
    const unsigned long long* s2p = reinterpret_cast<const unsigned long long*>(&sm2[0][0]);

    for (int cs = start; cs < end; cs += 8) {
        const int cnt = min(8, end - cs);

        // Stage duplicated sentence scalars into shared
        for (int t = tid; t < 8 * Cc; t += TPB) {
            int s = t >> 8;            // Cc == 256
            int c = t & (Cc - 1);
            float a = 0.f, w = 0.f;
            if (s < cnt) {
                a = g_sn1[(size_t)(cs + s) * Cc + c];
                w = g_sn2[(size_t)(cs + s) * Cc + c];
            }
            sm1[s][c] = make_float2(a, a);
            sm2[s][c] = make_float2(w, w);
        }
        __syncthreads();

        unsigned long long acc1[8], acc2[8];
        unsigned long long nn1 = 0ull, nn2 = 0ull;
        #pragma unroll
        for (int s = 0; s < 8; s++) { acc1[s] = 0ull; acc2[s] = 0ull; }

        #pragma unroll 4
        for (int c = 0; c < Cc; c++) {
            const unsigned long long a = v1[(size_t)c * (NN / 2)];
            const unsigned long long w = v2[(size_t)c * (NN / 2)];
            FFMA2(nn1, a, a);
            FFMA2(nn2, w, w);
            #pragma unroll
            for (int s = 0; s < 8; s++) {
                FFMA2(acc1[s], a, s1p[s * Cc + c]);
                FFMA2(acc2[s], w, s2p[s * Cc + c]);
            }
        }

        // Epilogue: per-column inverse norms, then per-sentence outputs
        const float i1lo = 1.f / fmaxf(sqrtf(f2lo(nn1)), EPSN);
        const float i1hi = 1.f / fmaxf(sqrtf(f2hi(nn1)), EPSN);
        const float i2lo = 1.f / fmaxf(sqrtf(f2lo(nn2)), EPSN);
        const float i2hi = 1.f / fmaxf(sqrtf(f2hi(nn2)), EPSN);

        for (int s = 0; s < cnt; s++) {
            const size_t srow = (size_t)(cs + s);
            const float d1lo = f2lo(acc1[s]) * i1lo;
            const float d1hi = f2hi(acc1[s]) * i1hi;
            const float lglo = SCALE * d1lo;
            const float lghi = SCALE * d1hi;
            out[srow * NN + ij0]     = lglo;
            out[srow * NN + ij0 + 1] = lghi;

            const float ioulo = m0 / (1.f + __expf(-lglo));
            const float iouhi = m1 / (1.f + __expf(-lghi));
            const float d2lo = f2lo(acc2[s]) * i2lo;
            const float d2hi = f2hi(acc2[s]) * i2hi;
            const float conlo = fmaxf((d2lo + 1.f) * 0.5f * m0, 0.f);
            const float conhi = fmaxf((d2hi + 1.f) * 0.5f * m1, 0.f);
            out[(size_t)Ss * NN + srow * NN + ij0]     = sqrtf(conlo) * ioulo;
            out[(size_t)Ss * NN + srow * NN + ij0 + 1] = sqrtf(conhi) * iouhi;
        }
        __syncthreads();
    }
}

// ---------------------------------------------------------------------------
extern "C" void kernel_launch(void* const* d_in, const int* in_sizes, int n_in,
                              void* d_out, int out_size) {
    const float* vf1  = (const float*)d_in[0];
    const float* vf2  = (const float*)d_in[1];
    const float* sf1  = (const float*)d_in[2];
    const float* sf2  = (const float*)d_in[3];
    const float* mask = (const float*)d_in[4];
    const int*   nums = (const int*)d_in[5];
    float* out = (float*)d_out;

    prep_kernel<<<(2 * Ss) / 8, 256>>>(sf1, sf2, nums);
    score_kernel<<<dim3(NN / (2 * TPB), Bv), TPB>>>(vf1, vf2, mask, out);
}

// round 2
// speedup vs baseline: 2.3578x; 2.3578x over previous
#include <cuda_runtime.h>
#include <math.h>

// Fixed problem shapes
#define Bv   16
#define Cc   256
#define Nn   64
#define NN   4096
#define Ss   128
#define EPSN 1e-12f
#define SCALE 10.0f
#define TPB  512     // 4 teams x 128 threads

typedef unsigned long long ull;

// Scratch: normalized sentence features + offsets
__device__ float g_sn1[Ss * Cc];
__device__ float g_sn2[Ss * Cc];
__device__ int   g_off[Bv + 1];

// Packed dual-fp32 FMA / ADD (Blackwell)
#define FFMA2(acc, a, bb) \
    asm("fma.rn.f32x2 %0, %1, %2, %0;" : "+l"(acc) : "l"(a), "l"(bb))
#define FADD2(dst, a, bb) \
    asm("add.rn.f32x2 %0, %1, %2;" : "=l"(dst) : "l"(a), "l"(bb))

__device__ __forceinline__ float f2lo(ull x) {
    return __uint_as_float((unsigned)(x & 0xffffffffu));
}
__device__ __forceinline__ float f2hi(ull x) {
    return __uint_as_float((unsigned)(x >> 32));
}

// ---------------------------------------------------------------------------
// Kernel 1: normalize sentence features (warp per row) + prefix offsets
// ---------------------------------------------------------------------------
__global__ void prep_kernel(const float* __restrict__ sf1,
                            const float* __restrict__ sf2,
                            const int*   __restrict__ nums) {
    if (blockIdx.x == 0 && threadIdx.x == 0) {
        int acc = 0;
        g_off[0] = 0;
        #pragma unroll
        for (int i = 0; i < Bv; i++) { acc += nums[i]; g_off[i + 1] = acc; }
    }
    int warp = threadIdx.x >> 5;
    int lane = threadIdx.x & 31;
    int row  = blockIdx.x * 8 + warp;   // 2S rows
    const float* src;
    float* dst;
    if (row < Ss) { src = sf1 + (size_t)row * Cc;        dst = g_sn1 + (size_t)row * Cc; }
    else          { src = sf2 + (size_t)(row - Ss) * Cc; dst = g_sn2 + (size_t)(row - Ss) * Cc; }

    float v[8];
    float sum = 0.f;
    #pragma unroll
    for (int k = 0; k < 8; k++) {
        v[k] = src[lane + 32 * k];
        sum += v[k] * v[k];
    }
    #pragma unroll
    for (int o = 16; o; o >>= 1) sum += __shfl_xor_sync(0xffffffffu, sum, o);
    float inv = 1.f / fmaxf(sqrtf(sum), EPSN);
    #pragma unroll
    for (int k = 0; k < 8; k++) dst[lane + 32 * k] = v[k] * inv;
}

// ---------------------------------------------------------------------------
// Kernel 2: fused dual-space scoring, 4-team split for occupancy.
// Block = 512 thr = 4 teams x 128. team = (space sp, channel-half ch).
// Each team accumulates partial dots over its 128 channels of its space.
// Video feats read exactly once from HBM. Partials combined via smem,
// team 0 runs the full fused epilogue.
// grid = (16 col-groups, 16 videos); each thread owns 2 adjacent columns.
// ---------------------------------------------------------------------------
__global__ __launch_bounds__(TPB, 2) void score_kernel(
    const float* __restrict__ vf1,
    const float* __restrict__ vf2,
    const float* __restrict__ mask2d,
    float* __restrict__ out) {

    // 32 KB: phase A = sentence scalars (duplicated pairs, sentence-major
    // inner: index (spp*256+c)*8+s); phase B = partial-sum scratch
    // ((team-1)*128+ttid)*9 + k, 27648 B.
    __shared__ ull buf[4096];

    const int tid  = threadIdx.x;
    const int team = tid >> 7;       // 0..3
    const int ttid = tid & 127;
    const int sp   = team >> 1;      // feature space
    const int ch   = team & 1;       // channel half
    const int b    = blockIdx.y;
    const int ij0  = blockIdx.x * 256 + 2 * ttid;

    const int start = g_off[b];
    int end = g_off[b + 1];
    if (end > Ss) end = Ss;
    if (start >= end) return;        // uniform per block

    const float* vf = (sp == 0) ? vf1 : vf2;
    const ull* __restrict__ v = reinterpret_cast<const ull*>(
        vf + ((size_t)b * Cc + (size_t)ch * 128) * NN + ij0);

    const float m0 = mask2d[ij0];
    const float m1 = mask2d[ij0 + 1];

    const ull* __restrict__ sb = buf + (size_t)(sp * 256 + ch * 128) * 8;

    for (int cs = start; cs < end; cs += 8) {
        const int cnt = min(8, end - cs);

        // Phase A: stage duplicated sentence scalars (all 512 threads)
        for (int e = tid; e < 2 * Cc * 8; e += TPB) {
            const int s   = e & 7;
            const int c   = (e >> 3) & (Cc - 1);
            const int spp = e >> 11;
            float val = 0.f;
            if (s < cnt)
                val = (spp == 0 ? g_sn1 : g_sn2)[(size_t)(cs + s) * Cc + c];
            float2 d = make_float2(val, val);
            buf[e] = *reinterpret_cast<ull*>(&d);
        }
        __syncthreads();

        ull acc[8];
        #pragma unroll
        for (int s = 0; s < 8; s++) acc[s] = 0ull;
        ull nrm = 0ull;

        #pragma unroll 8
        for (int k = 0; k < 128; k++) {
            const ull a = v[(size_t)k * (NN / 2)];
            FFMA2(nrm, a, a);
            const ulonglong2* p =
                reinterpret_cast<const ulonglong2*>(sb + k * 8);
            const ulonglong2 q0 = p[0];
            const ulonglong2 q1 = p[1];
            const ulonglong2 q2 = p[2];
            const ulonglong2 q3 = p[3];
            FFMA2(acc[0], a, q0.x); FFMA2(acc[1], a, q0.y);
            FFMA2(acc[2], a, q1.x); FFMA2(acc[3], a, q1.y);
            FFMA2(acc[4], a, q2.x); FFMA2(acc[5], a, q2.y);
            FFMA2(acc[6], a, q3.x); FFMA2(acc[7], a, q3.y);
        }
        __syncthreads();   // done reading sentence smem

        // Phase B: teams 1..3 publish partials
        if (team != 0) {
            ull* r = buf + ((size_t)(team - 1) * 128 + ttid) * 9;
            #pragma unroll
            for (int s = 0; s < 8; s++) r[s] = acc[s];
            r[8] = nrm;
        }
        __syncthreads();

        if (team == 0) {
            const ull* r1 = buf + ((size_t)0 * 128 + ttid) * 9; // sp0, ch1
            const ull* r2 = buf + ((size_t)1 * 128 + ttid) * 9; // sp1, ch0
            const ull* r3 = buf + ((size_t)2 * 128 + ttid) * 9; // sp1, ch1

            ull t1[8], t2[8], n1, n2;
            #pragma unroll
            for (int s = 0; s < 8; s++) {
                FADD2(t1[s], acc[s], r1[s]);
                FADD2(t2[s], r2[s], r3[s]);
            }
            FADD2(n1, nrm, r1[8]);
            FADD2(n2, r2[8], r3[8]);

            const float i1lo = 1.f / fmaxf(sqrtf(f2lo(n1)), EPSN);
            const float i1hi = 1.f / fmaxf(sqrtf(f2hi(n1)), EPSN);
            const float i2lo = 1.f / fmaxf(sqrtf(f2lo(n2)), EPSN);
            const float i2hi = 1.f / fmaxf(sqrtf(f2hi(n2)), EPSN);

            for (int s = 0; s < cnt; s++) {
                const size_t srow = (size_t)(cs + s);
                const float lglo = SCALE * (f2lo(t1[s]) * i1lo);
                const float lghi = SCALE * (f2hi(t1[s]) * i1hi);
                *reinterpret_cast<float2*>(out + srow * NN + ij0) =
                    make_float2(lglo, lghi);

                const float ioulo = m0 / (1.f + __expf(-lglo));
                const float iouhi = m1 / (1.f + __expf(-lghi));
                const float conlo =
                    fmaxf((f2lo(t2[s]) * i2lo + 1.f) * 0.5f * m0, 0.f);
                const float conhi =
                    fmaxf((f2hi(t2[s]) * i2hi + 1.f) * 0.5f * m1, 0.f);
                *reinterpret_cast<float2*>(out + (size_t)Ss * NN + srow * NN + ij0) =
                    make_float2(sqrtf(conlo) * ioulo, sqrtf(conhi) * iouhi);
            }
        }
        __syncthreads();   // scratch/sentence smem safe to overwrite
    }
}

// ---------------------------------------------------------------------------
extern "C" void kernel_launch(void* const* d_in, const int* in_sizes, int n_in,
                              void* d_out, int out_size) {
    const float* vf1  = (const float*)d_in[0];
    const float* vf2  = (const float*)d_in[1];
    const float* sf1  = (const float*)d_in[2];
    const float* sf2  = (const float*)d_in[3];
    const float* mask = (const float*)d_in[4];
    const int*   nums = (const int*)d_in[5];
    float* out = (float*)d_out;

    prep_kernel<<<(2 * Ss) / 8, 256>>>(sf1, sf2, nums);
    score_kernel<<<dim3(NN / 256, Bv), TPB>>>(vf1, vf2, mask, out);
}